// round 8
// baseline (speedup 1.0000x reference)
#include <cuda_runtime.h>

// Fused: channel-mix (w1) -> double-unfold 1D conv along W (w0, torch-style
// two-stage zero-pad masks) -> roll(+1) along H.
//
// x  : [128, 56, 56] f32, w0 : [32,2,3,3], w1 : [4,64], out : [128,56,56]
//
// out[l*4+p, o, n] = sum_{j,i,k} w0[l,j,i,k] * t4[p,j,(o-1)%56, n+i+k-2]
//                    * [0 <= n+k-1 < 56] * [0 <= n+i+k-2 < 56]
// t4[p,j,h,w] = sum_c w1[p,c] * x[2c+j, h, w]
//
// Combined weights per (l,j), grouped by d=i+k:
//   r0=w(0,0) [t4(n-2), n>=2]   r1=w(0,1)+w(1,0) [t4(n-1), n>=1]
//   r2=w(1,1) [t4(n)]           r3=w(2,0) [t4(n), n>=1]
//   r4=w(0,2) [t4(n), n<=54]    r5=w(1,2)+w(2,1) [t4(n+1), n<=54]
//   r6=w(2,2) [t4(n+2), n<=53]
// Center fold wc = r2+r3+r4, valid for 1<=n<=54; fixups at n=0 (drop r3)
// and n=55 (drop r4).
//
// Grid 112 = 56 rows x 2 p-halves. Block 256. Critical path:
//   [wcs prologue || stage1: 64 LDG (L2) + 128 FMA on 112 threads, dual
//    p-accumulators per x load] -> one barrier -> stage2 (register conv) -> STG.

#define NT 256

__global__ __launch_bounds__(NT, 1) void fused_shuffleconv3(
    const float* __restrict__ x,
    const float* __restrict__ w0,
    const float* __restrict__ w1,
    float* __restrict__ out)
{
    __shared__ float t4s[4 * 58];     // rows (pl*2+j), stride 58 (bank-conflict-free)
    __shared__ float wcs[32 * 16];    // combined weights [l][j*7+r], padded to 16

    const int tid  = threadIdx.x;
    const int o    = blockIdx.x >> 1;
    const int ph   = blockIdx.x & 1;            // p in {2ph, 2ph+1}
    const int hsrc = (o + 55) % 56;             // roll(+1): out row o <- y row o-1

    // ---- combined weights (all threads; overlaps stage-1 load latency) ----
    #pragma unroll
    for (int e = tid; e < 448; e += NT) {       // 32 l * 14 entries
        int l = e / 14, q = e % 14;
        int j = q / 7,  r = q % 7;
        const float* wb = w0 + (l * 2 + j) * 9; // [3][3], idx = i*3+k
        float v;
        switch (r) {
            case 0:  v = wb[0];          break;
            case 1:  v = wb[1] + wb[3];  break;
            case 2:  v = wb[4];          break;
            case 3:  v = wb[6];          break;
            case 4:  v = wb[2];          break;
            case 5:  v = wb[5] + wb[7];  break;
            default: v = wb[8];          break;
        }
        wcs[l * 16 + j * 7 + r] = v;
    }

    // ---- stage 1: threads 0..111 = (j, m); both p accumulators per x load ----
    if (tid < 112) {
        const int j = tid / 56;
        const int m = tid - j * 56;
        const float* xb = x + j * 3136 + hsrc * 56 + m;   // + c*6272 per c
        const float4* w1a = (const float4*)(w1 + (2 * ph    ) * 64);
        const float4* w1b = (const float4*)(w1 + (2 * ph + 1) * 64);
        float acc0 = 0.f, acc1 = 0.f;
        #pragma unroll
        for (int c4 = 0; c4 < 16; c4++) {
            float4 wa = w1a[c4];
            float4 wb4 = w1b[c4];
            const float* xc = xb + c4 * 4 * 6272;
            float x0 = xc[0];
            float x1 = xc[6272];
            float x2 = xc[2 * 6272];
            float x3 = xc[3 * 6272];
            acc0 = fmaf(wa.x,  x0, acc0);  acc1 = fmaf(wb4.x, x0, acc1);
            acc0 = fmaf(wa.y,  x1, acc0);  acc1 = fmaf(wb4.y, x1, acc1);
            acc0 = fmaf(wa.z,  x2, acc0);  acc1 = fmaf(wb4.z, x2, acc1);
            acc0 = fmaf(wa.w,  x3, acc0);  acc1 = fmaf(wb4.w, x3, acc1);
        }
        t4s[(0 + j) * 58 + m] = acc0;     // pl=0 rows: 0(j0), 1(j1)
        t4s[(2 + j) * 58 + m] = acc1;     // pl=1 rows: 2(j0), 3(j1)
    }
    __syncthreads();

    // ---- stage 2: thread = (c, g): c -> (l, pl), g -> 14-col quarter ----
    const int c  = tid >> 2;              // 0..63
    const int g  = tid & 3;               // 0..3
    const int l  = c >> 1;
    const int pl = c & 1;
    const int nbase = g * 14;

    const float* tb0 = t4s + (pl * 2) * 58;   // j=0 row
    const float* tb1 = tb0 + 58;              // j=1 row

    float T0[18], T1[18];
    #pragma unroll
    for (int u = 0; u < 18; u++) {
        int gc = nbase - 2 + u;
        int ci = gc < 0 ? 0 : (gc > 55 ? 55 : gc);
        bool ok = (gc >= 0) & (gc <= 55);
        float v0 = tb0[ci], v1 = tb1[ci];
        T0[u] = ok ? v0 : 0.f;
        T1[u] = ok ? v1 : 0.f;
    }

    const float4* wp = (const float4*)(wcs + l * 16);
    float4 A = wp[0];   // j0: r0 r1 r2 r3
    float4 B = wp[1];   // j0: r4 r5 r6 | j1: r0
    float4 C = wp[2];   // j1: r1 r2 r3 r4
    float4 D = wp[3];   // j1: r5 r6 - -
    float wc0 = A.z + A.w + B.x;          // j0 center
    float wc1 = C.y + C.z + C.w;          // j1 center

    float obuf[14];
    #pragma unroll
    for (int i = 0; i < 14; i++) {
        float acc;
        acc = fmaf(A.x, T0[i],     0.f);
        acc = fmaf(A.y, T0[i + 1], acc);
        acc = fmaf(wc0, T0[i + 2], acc);
        acc = fmaf(B.y, T0[i + 3], acc);
        acc = fmaf(B.z, T0[i + 4], acc);
        acc = fmaf(B.w, T1[i],     acc);
        acc = fmaf(C.x, T1[i + 1], acc);
        acc = fmaf(wc1, T1[i + 2], acc);
        acc = fmaf(D.x, T1[i + 3], acc);
        acc = fmaf(D.y, T1[i + 4], acc);
        obuf[i] = acc;
    }
    // edge fixups: n=0 drops r3 from center, n=55 drops r4
    if (g == 0) obuf[0]  -= A.w * T0[2]  + C.z * T1[2];
    if (g == 3) obuf[13] -= B.x * T0[15] + C.w * T1[15];

    const int ch = l * 4 + 2 * ph + pl;
    float* ob = out + ch * 3136 + o * 56 + nbase;
    #pragma unroll
    for (int k = 0; k < 7; k++)
        *(float2*)(ob + 2 * k) = make_float2(obuf[2 * k], obuf[2 * k + 1]);
}

extern "C" void kernel_launch(void* const* d_in, const int* in_sizes, int n_in,
                              void* d_out, int out_size) {
    const float* x  = (const float*)d_in[0];
    const float* w0 = (const float*)d_in[1];
    const float* w1 = (const float*)d_in[2];
    float* out = (float*)d_out;
    fused_shuffleconv3<<<112, NT>>>(x, w0, w1, out);
}